// round 8
// baseline (speedup 1.0000x reference)
#include <cuda_runtime.h>

#define NCHUNKS 32
#define ROWS    64
#define THREADS 1024
#define MAX_ATOMS   16384
#define MAX_CLAUSES 4096

// Padded meta: every clause padded to a multiple of 4 atoms (identity pads).
// Per atom: {A', B', (fid*256)|flushFlag(bit31 on group-end-of-clause atom3),
//            gate*leaf[cid] on that same atom3, else 0}
// arg = A'*x[fid] + B' ; e = exp2(arg) ; clause = 1/prod(1+e)
__device__ float4 g_meta[MAX_ATOMS];
__device__ int    g_chunk_start[NCHUNKS + 1];  // padded, group- & clause-aligned
__device__ float  g_empty[NCHUNKS];            // sum g over EMPTY clauses per chunk
__device__ int    g_clause_src[MAX_CLAUSES];
__device__ int    g_clause_dst[MAX_CLAUSES];
__device__ int    g_clause_len[MAX_CLAUSES];

__device__ __forceinline__ float ex2a(float a) {
    float r; asm("ex2.approx.f32 %0, %1;" : "=f"(r) : "f"(a)); return r;
}
__device__ __forceinline__ float rcpa(float a) {
    float r; asm("rcp.approx.f32 %0, %1;" : "=f"(r) : "f"(a)); return r;
}

// One block. thread c = clause c: locate atoms, pad length, scan offsets.
__global__ void cln_scan(const float* __restrict__ leaf,
                         const float* __restrict__ gate,
                         const int* __restrict__ cids,
                         int n_atoms, int n_clauses, int cpc) {
    __shared__ int s[MAX_CLAUSES > 1024 ? 1024 : MAX_CLAUSES];
    int c = threadIdx.x;
    int len = 0, lo = 0;
    if (c < n_clauses) {
        int hi = n_atoms;
        while (lo < hi) { int m = (lo + hi) >> 1; if (cids[m] < c) lo = m + 1; else hi = m; }
        int lo2 = lo, hi2 = n_atoms;
        while (lo2 < hi2) { int m = (lo2 + hi2) >> 1; if (cids[m] < c + 1) lo2 = m + 1; else hi2 = m; }
        len = lo2 - lo;
        if (len == 0) atomicAdd(&g_empty[c / cpc], gate[c] * leaf[c]);
    }
    int plen = (len + 3) & ~3;
    s[c] = plen;
    __syncthreads();
    // inclusive scan (Hillis-Steele)
    for (int off = 1; off < blockDim.x; off <<= 1) {
        int v = (c >= off) ? s[c - off] : 0;
        __syncthreads();
        s[c] += v;
        __syncthreads();
    }
    if (c < n_clauses) {
        int excl = s[c] - plen;
        g_clause_src[c] = lo;
        g_clause_dst[c] = excl;
        g_clause_len[c] = len;
        if (c % cpc == 0)      g_chunk_start[c / cpc] = excl;
        if (c == n_clauses - 1) g_chunk_start[NCHUNKS] = s[c];
    }
}

// One thread per clause: write its padded meta run.
__global__ void cln_build(const float* __restrict__ w,
                          const float* __restrict__ eta,
                          const float* __restrict__ leaf,
                          const float* __restrict__ gate,
                          const int* __restrict__ fid,
                          const int* __restrict__ csgn,
                          int n_clauses) {
    int c = blockIdx.x * blockDim.x + threadIdx.x;
    if (c >= n_clauses) return;
    int len = g_clause_len[c];
    if (len == 0) return;
    int src = g_clause_src[c], dst = g_clause_dst[c];
    int plen = (len + 3) & ~3;
    const float L2E = 1.4426950408889634f;
    for (int j = 0; j < plen; ++j) {
        float A2, B2, g = 0.f;
        int fz;
        if (j < len) {
            int i = src + j;
            float sB = (csgn[i] == 0) ? -100.0f : 100.0f;
            A2 = -sB * w[i] * L2E;
            B2 = -sB * (0.01f - eta[i]) * L2E;
            fz = fid[i] << 8;                 // byte offset into feature-major tile
        } else {                              // identity pad: e -> ~0, p unchanged
            A2 = 0.f; B2 = -1000.f; fz = 0;
        }
        if (j == plen - 1) {                  // group-end == clause-end here
            fz |= 0x80000000;
            g = gate[c] * leaf[c];
        }
        g_meta[dst + j] = make_float4(A2, B2, __int_as_float(fz), g);
    }
}

__global__ __launch_bounds__(THREADS, 1)
void cln_main(const float* __restrict__ x, float* __restrict__ y, int nfeat) {
    extern __shared__ float xs[];            // feature-major: xs[feat*ROWS + row]
    __shared__ float ys[ROWS];

    const int rowBase = blockIdx.x * ROWS;

    const int n4 = nfeat >> 2;
    for (int i = threadIdx.x; i < n4 * ROWS; i += THREADS) {
        int f4 = i >> 6, row = i & (ROWS - 1);
        float4 v = reinterpret_cast<const float4*>(
                       x + (size_t)(rowBase + row) * nfeat)[f4];
        xs[(4 * f4 + 0) * ROWS + row] = v.x;
        xs[(4 * f4 + 1) * ROWS + row] = v.y;
        xs[(4 * f4 + 2) * ROWS + row] = v.z;
        xs[(4 * f4 + 3) * ROWS + row] = v.w;
    }
    if (threadIdx.x < ROWS) ys[threadIdx.x] = 0.f;
    __syncthreads();

    const int chunk = threadIdx.x >> 5;      // warp == chunk
    const int lane  = threadIdx.x & 31;

    const char* xbase = (const char*)xs + lane * 8;   // rows 2*lane, 2*lane+1
    const float ec = g_empty[chunk];
    float y0 = ec, y1 = ec;
    float p0 = 1.f, p1 = 1.f;

    const float4* __restrict__ mp = g_meta + g_chunk_start[chunk];
    const int n = g_chunk_start[chunk + 1] - g_chunk_start[chunk];  // multiple of 4

#define LOADX(f)   (*(const float2*)(xbase + (f)))
#define EXPE(mm, xv) fmaxf(ex2a(fmaf((mm).x, (xv), (mm).y)), 1e-37f)

    for (int i = 0; i < n; i += 4) {
        float4 m0 = mp[i], m1 = mp[i + 1], m2 = mp[i + 2], m3 = mp[i + 3];
        int fz3 = __float_as_int(m3.z);
        float2 x0 = LOADX(__float_as_int(m0.z));
        float2 x1 = LOADX(__float_as_int(m1.z));
        float2 x2 = LOADX(__float_as_int(m2.z));
        float2 x3 = LOADX(fz3 & 0x7fffffff);

        float e00 = EXPE(m0, x0.x), e01 = EXPE(m1, x1.x);
        float e02 = EXPE(m2, x2.x), e03 = EXPE(m3, x3.x);
        float e10 = EXPE(m0, x0.y), e11 = EXPE(m1, x1.y);
        float e12 = EXPE(m2, x2.y), e13 = EXPE(m3, x3.y);

        // pure FFMA chains — no per-atom resets needed (clauses group-aligned)
        p0 = fmaf(p0, e00, p0); p0 = fmaf(p0, e01, p0);
        p0 = fmaf(p0, e02, p0); p0 = fmaf(p0, e03, p0);
        p1 = fmaf(p1, e10, p1); p1 = fmaf(p1, e11, p1);
        p1 = fmaf(p1, e12, p1); p1 = fmaf(p1, e13, p1);

        if (fz3 < 0) {                       // clause ends at this group
            y0 = fmaf(m3.w, rcpa(p0), y0);
            y1 = fmaf(m3.w, rcpa(p1), y1);
            p0 = 1.f; p1 = 1.f;
        }
    }

    atomicAdd(&ys[2 * lane],     y0);
    atomicAdd(&ys[2 * lane + 1], y1);
    __syncthreads();
    if (threadIdx.x < ROWS)
        y[rowBase + threadIdx.x] = ys[threadIdx.x];
}

extern "C" void kernel_launch(void* const* d_in, const int* in_sizes, int n_in,
                              void* d_out, int out_size) {
    const float* x    = (const float*)d_in[0];
    const float* w    = (const float*)d_in[1];
    const float* eta  = (const float*)d_in[2];
    const float* leaf = (const float*)d_in[3];
    const float* gate = (const float*)d_in[4];
    const int*   fid  = (const int*)d_in[5];
    const int*   csgn = (const int*)d_in[6];
    const int*   cids = (const int*)d_in[7];

    const int n_atoms   = in_sizes[1];
    const int n_clauses = in_sizes[3];
    const int batch     = out_size;
    const int nfeat     = in_sizes[0] / batch;
    const int cpc       = n_clauses / NCHUNKS;

    void* empty_ptr = nullptr;
    cudaGetSymbolAddress(&empty_ptr, g_empty);
    cudaMemsetAsync(empty_ptr, 0, NCHUNKS * sizeof(float));

    int scan_threads = n_clauses <= 1024 ? n_clauses : 1024;
    cln_scan<<<1, scan_threads>>>(leaf, gate, cids, n_atoms, n_clauses, cpc);
    cln_build<<<(n_clauses + 255) / 256, 256>>>(w, eta, leaf, gate, fid, csgn,
                                                n_clauses);

    size_t smem = (size_t)nfeat * ROWS * sizeof(float);
    cudaFuncSetAttribute(cln_main, cudaFuncAttributeMaxDynamicSharedMemorySize,
                         (int)smem);
    cln_main<<<batch / ROWS, THREADS, smem>>>(x, (float*)d_out, nfeat);
}

// round 9
// speedup vs baseline: 1.0450x; 1.0450x over previous
#include <cuda_runtime.h>

#define NCHUNKS 32
#define ROWS    64
#define THREADS 1024
#define MAX_ATOMS   16384
#define MAX_CLAUSES 4096

// Padded meta: every clause padded to a multiple of 4 atoms (identity pads).
// Per atom: {A', B', (fid*256)|flushFlag(bit31 on last padded slot),
//            gate*leaf[cid] on that slot, else 0}
// arg = A'*x[fid] + B' ; e = exp2(arg) ; clause = 1/prod(1+e)
__device__ float4 g_meta[MAX_ATOMS];
__device__ int    g_chunk_start[NCHUNKS + 1];  // padded, group- & clause-aligned
__device__ float  g_empty[NCHUNKS];            // sum g over EMPTY clauses per chunk

__device__ __forceinline__ float ex2a(float a) {
    float r; asm("ex2.approx.f32 %0, %1;" : "=f"(r) : "f"(a)); return r;
}
__device__ __forceinline__ float rcpa(float a) {
    float r; asm("rcp.approx.f32 %0, %1;" : "=f"(r) : "f"(a)); return r;
}

// Fused single-block setup: cids staged in smem, searches in smem, scan in
// smem, atom-parallel meta build. Replaces the slow scan+build pair of R8.
__global__ void cln_setup(const float* __restrict__ w,
                          const float* __restrict__ eta,
                          const float* __restrict__ leaf,
                          const float* __restrict__ gate,
                          const int* __restrict__ fid,
                          const int* __restrict__ csgn,
                          const int* __restrict__ cids,
                          int n_atoms, int n_clauses, int cpc) {
    extern __shared__ int sm[];
    int*   s_cids = sm;                      // n_atoms
    int*   s_src  = sm + n_atoms;            // n_clauses
    int*   s_dst  = s_src + n_clauses;       // n_clauses
    int*   s_scan = s_dst + n_clauses;       // n_clauses (plen -> incl scan)
    float* s_g    = (float*)(s_scan + n_clauses);

    const int tid = threadIdx.x;
    const float L2E = 1.4426950408889634f;

    for (int i = tid; i < n_atoms; i += blockDim.x) s_cids[i] = cids[i];
    __syncthreads();

    int len = 0, lo = 0, plen = 0;
    if (tid < n_clauses) {
        int hi = n_atoms;
        while (lo < hi) { int m = (lo + hi) >> 1; if (s_cids[m] < tid) lo = m + 1; else hi = m; }
        int lo2 = lo, hi2 = n_atoms;
        while (lo2 < hi2) { int m = (lo2 + hi2) >> 1; if (s_cids[m] < tid + 1) lo2 = m + 1; else hi2 = m; }
        len = lo2 - lo;
        plen = (len + 3) & ~3;
        float g = gate[tid] * leaf[tid];
        s_src[tid] = lo;
        s_scan[tid] = plen;
        s_g[tid] = g;
        if (len == 0) atomicAdd(&g_empty[tid / cpc], g);
    }
    __syncthreads();
    // inclusive scan of padded lengths (Hillis-Steele)
    for (int off = 1; off < n_clauses; off <<= 1) {
        int v = 0;
        if (tid < n_clauses && tid >= off) v = s_scan[tid - off];
        __syncthreads();
        if (tid < n_clauses) s_scan[tid] += v;
        __syncthreads();
    }
    if (tid < n_clauses) {
        int excl = s_scan[tid] - plen;
        s_dst[tid] = excl;
        if (tid % cpc == 0)       g_chunk_start[tid / cpc] = excl;
        if (tid == n_clauses - 1) g_chunk_start[NCHUNKS]   = s_scan[tid];
    }
    __syncthreads();

    // atom-parallel meta build (coalesced loads, computed scatter)
    for (int i = tid; i < n_atoms; i += blockDim.x) {
        int c   = s_cids[i];
        int dst = s_dst[c];
        int j   = i - s_src[c];
        int plenc = s_scan[c] - dst;
        float sB = (csgn[i] == 0) ? -100.0f : 100.0f;
        float A2 = -sB * w[i] * L2E;
        float B2 = -sB * (0.01f - eta[i]) * L2E;
        int fz = fid[i] << 8;
        float g = 0.f;
        if (j == plenc - 1) { fz |= 0x80000000; g = s_g[c]; }
        g_meta[dst + j] = make_float4(A2, B2, __int_as_float(fz), g);
    }
    // pads (<=3 per clause; identity atoms: e -> ~0)
    if (tid < n_clauses && len > 0) {
        int dst = s_dst[tid];
        for (int j = len; j < plen; ++j) {
            int fz = 0; float g = 0.f;
            if (j == plen - 1) { fz = 0x80000000; g = s_g[tid]; }
            g_meta[dst + j] = make_float4(0.f, -1000.f, __int_as_float(fz), g);
        }
    }
}

__global__ __launch_bounds__(THREADS, 1)
void cln_main(const float* __restrict__ x, float* __restrict__ y, int nfeat) {
    extern __shared__ float xs[];            // feature-major: xs[feat*ROWS + row]
    __shared__ float ys[ROWS];

    const int rowBase = blockIdx.x * ROWS;

    const int n4 = nfeat >> 2;
    for (int i = threadIdx.x; i < n4 * ROWS; i += THREADS) {
        int f4 = i >> 6, row = i & (ROWS - 1);
        float4 v = reinterpret_cast<const float4*>(
                       x + (size_t)(rowBase + row) * nfeat)[f4];
        xs[(4 * f4 + 0) * ROWS + row] = v.x;
        xs[(4 * f4 + 1) * ROWS + row] = v.y;
        xs[(4 * f4 + 2) * ROWS + row] = v.z;
        xs[(4 * f4 + 3) * ROWS + row] = v.w;
    }
    if (threadIdx.x < ROWS) ys[threadIdx.x] = 0.f;
    __syncthreads();

    const int chunk = threadIdx.x >> 5;      // warp == chunk
    const int lane  = threadIdx.x & 31;

    const char* xbase = (const char*)xs + lane * 8;   // rows 2*lane, 2*lane+1
    const float ec = g_empty[chunk];
    float y0 = ec, y1 = ec;
    float p0 = 1.f, p1 = 1.f;

    const float4* __restrict__ mp = g_meta + g_chunk_start[chunk];
    const int n = g_chunk_start[chunk + 1] - g_chunk_start[chunk];  // multiple of 4

#define LOADX(f)   (*(const float2*)(xbase + (f)))
#define EXPE(mm, xv) fmaxf(ex2a(fmaf((mm).x, (xv), (mm).y)), 1e-37f)

    for (int i = 0; i < n; i += 4) {
        float4 m0 = mp[i], m1 = mp[i + 1], m2 = mp[i + 2], m3 = mp[i + 3];
        int fz3 = __float_as_int(m3.z);
        float2 x0 = LOADX(__float_as_int(m0.z));
        float2 x1 = LOADX(__float_as_int(m1.z));
        float2 x2 = LOADX(__float_as_int(m2.z));
        float2 x3 = LOADX(fz3 & 0x7fffffff);

        float e00 = EXPE(m0, x0.x), e01 = EXPE(m1, x1.x);
        float e02 = EXPE(m2, x2.x), e03 = EXPE(m3, x3.x);
        float e10 = EXPE(m0, x0.y), e11 = EXPE(m1, x1.y);
        float e12 = EXPE(m2, x2.y), e13 = EXPE(m3, x3.y);

        // pure FFMA chains — no per-atom resets (clauses are group-aligned)
        p0 = fmaf(p0, e00, p0); p0 = fmaf(p0, e01, p0);
        p0 = fmaf(p0, e02, p0); p0 = fmaf(p0, e03, p0);
        p1 = fmaf(p1, e10, p1); p1 = fmaf(p1, e11, p1);
        p1 = fmaf(p1, e12, p1); p1 = fmaf(p1, e13, p1);

        if (fz3 < 0) {                       // clause ends at this group
            y0 = fmaf(m3.w, rcpa(p0), y0);
            y1 = fmaf(m3.w, rcpa(p1), y1);
            p0 = 1.f; p1 = 1.f;
        }
    }

    atomicAdd(&ys[2 * lane],     y0);
    atomicAdd(&ys[2 * lane + 1], y1);
    __syncthreads();
    if (threadIdx.x < ROWS)
        y[rowBase + threadIdx.x] = ys[threadIdx.x];
}

extern "C" void kernel_launch(void* const* d_in, const int* in_sizes, int n_in,
                              void* d_out, int out_size) {
    const float* x    = (const float*)d_in[0];
    const float* w    = (const float*)d_in[1];
    const float* eta  = (const float*)d_in[2];
    const float* leaf = (const float*)d_in[3];
    const float* gate = (const float*)d_in[4];
    const int*   fid  = (const int*)d_in[5];
    const int*   csgn = (const int*)d_in[6];
    const int*   cids = (const int*)d_in[7];

    const int n_atoms   = in_sizes[1];
    const int n_clauses = in_sizes[3];
    const int batch     = out_size;
    const int nfeat     = in_sizes[0] / batch;
    const int cpc       = n_clauses / NCHUNKS;

    void* empty_ptr = nullptr;
    cudaGetSymbolAddress(&empty_ptr, g_empty);
    cudaMemsetAsync(empty_ptr, 0, NCHUNKS * sizeof(float));

    size_t setup_smem = (size_t)n_atoms * 4 + (size_t)n_clauses * 16;
    cudaFuncSetAttribute(cln_setup, cudaFuncAttributeMaxDynamicSharedMemorySize,
                         (int)setup_smem);
    cln_setup<<<1, 1024, setup_smem>>>(w, eta, leaf, gate, fid, csgn, cids,
                                       n_atoms, n_clauses, cpc);

    size_t smem = (size_t)nfeat * ROWS * sizeof(float);
    cudaFuncSetAttribute(cln_main, cudaFuncAttributeMaxDynamicSharedMemorySize,
                         (int)smem);
    cln_main<<<batch / ROWS, THREADS, smem>>>(x, (float*)d_out, nfeat);
}

// round 10
// speedup vs baseline: 1.1977x; 1.1462x over previous
#include <cuda_runtime.h>

#define NCHUNKS 32
#define ROWS    64
#define THREADS 1024
#define XPAD    257               // smem row stride in floats (conflict-free)
#define MAX_ATOMS   16384
#define MAX_CLAUSES 4096

// Packed per-atom metadata: {A', B', fid|lastFlag(bit31), gate*leaf[cid] if last}
// arg = A'*x[fid] + B' ; e = exp2(arg) = exp(-z) ; sigmoid(z) = 1/(1+e)
// clause value = 1 / prod(1+e) ; accumulated when lastFlag set.
__device__ float4 g_meta[MAX_ATOMS];
__device__ int    g_chunk_start[NCHUNKS + 1]; // clause-aligned atom ranges
__device__ float  g_empty[NCHUNKS];           // sum of g over EMPTY clauses per chunk

__device__ __forceinline__ float ex2a(float a) {
    float r; asm("ex2.approx.f32 %0, %1;" : "=f"(r) : "f"(a)); return r;
}
__device__ __forceinline__ float rcpa(float a) {
    float r; asm("rcp.approx.f32 %0, %1;" : "=f"(r) : "f"(a)); return r;
}

// Streaming setup: no binary searches anywhere. Atom i detects chunk
// boundaries it crosses and writes g_chunk_start directly.
__global__ void cln_setup(const float* __restrict__ w,
                          const float* __restrict__ eta,
                          const float* __restrict__ leaf,
                          const float* __restrict__ gate,
                          const int* __restrict__ fid,
                          const int* __restrict__ csgn,
                          const int* __restrict__ cids,
                          int n_atoms, int n_clauses, int cpc) {
    int i = blockIdx.x * blockDim.x + threadIdx.x;
    const float L2E = 1.4426950408889634f;   // log2(e)
    if (i >= n_atoms) return;

    int cid  = cids[i];
    int prev = (i == 0) ? -1 : cids[i - 1];
    int nxt  = (i == n_atoms - 1) ? n_clauses : cids[i + 1];

    float sB = (csgn[i] == 0) ? -100.0f : 100.0f;   // sign * B_CONST
    float A2 = -sB * w[i] * L2E;
    float B2 = -sB * (0.01f - eta[i]) * L2E;        // EPS = 0.01
    bool last = (nxt != cid);
    int fz = fid[i] | (last ? 0x80000000 : 0);
    float g = last ? gate[cid] * leaf[cid] : 0.f;
    g_meta[i] = make_float4(A2, B2, __int_as_float(fz), g);

    // chunk starts crossed at this atom: prev < k*cpc <= cid  ->  start = i
    for (int k = (prev + cpc) / cpc; k * cpc <= cid; ++k)
        g_chunk_start[k] = i;
    if (i == n_atoms - 1)
        for (int k = cid / cpc + 1; k <= NCHUNKS; ++k)
            g_chunk_start[k] = n_atoms;

    // empty clauses in (cid, nxt): product == 1, fold into g_empty
    if (last)
        for (int c = cid + 1; c < nxt; ++c)
            atomicAdd(&g_empty[c / cpc], gate[c] * leaf[c]);
    if (i == 0)
        for (int c = 0; c < cid; ++c)
            atomicAdd(&g_empty[c / cpc], gate[c] * leaf[c]);
}

__global__ __launch_bounds__(THREADS, 1)
void cln_main(const float* __restrict__ x, float* __restrict__ y, int nfeat) {
    extern __shared__ float xs[];            // ROWS * XPAD floats
    __shared__ float ys[ROWS];

    const int rowBase = blockIdx.x * ROWS;

    // Stage 64 rows of x into shared (coalesced float4 loads)
    const int n4f = nfeat >> 2;
    for (int i = threadIdx.x; i < ROWS * n4f; i += THREADS) {
        int row = i / n4f, f4 = i - row * n4f;
        float4 v = reinterpret_cast<const float4*>(
                       x + (size_t)(rowBase + row) * nfeat)[f4];
        float* d = xs + row * XPAD + (f4 << 2);
        d[0] = v.x; d[1] = v.y; d[2] = v.z; d[3] = v.w;
    }
    if (threadIdx.x < ROWS) ys[threadIdx.x] = 0.f;
    __syncthreads();

    const int chunk = threadIdx.x >> 5;    // warp == chunk, 0..31
    const int lane  = threadIdx.x & 31;

    const float* xr0 = xs + lane * XPAD;   // lane owns rows lane and lane+32
    const float ec = g_empty[chunk];
    float y0 = ec, y1 = ec;
    float p0 = 1.f, p1 = 1.f;              // p >= 1 always

    const float4* __restrict__ mp = g_meta + g_chunk_start[chunk];
    const int n = g_chunk_start[chunk + 1] - g_chunk_start[chunk];

    // e clamped away from 0 so p==inf never meets e==0 (no NaN); p may reach
    // inf, then rcp gives 0 which matches reference underflow-to-zero.
#define EVAL(mm, f, off) fmaxf(ex2a(fmaf((mm).x, xr0[(f) + (off)], (mm).y)), 1e-37f)

    const int n4 = n & ~3;
    float4 c0, c1, c2, c3;
    if (n4 > 0) { c0 = mp[0]; c1 = mp[1]; c2 = mp[2]; c3 = mp[3]; }

    for (int i = 0; i < n4; i += 4) {
        // software pipeline: prefetch next group while processing current
        int ip = (i + 4 < n4) ? (i + 4) : i;
        float4 d0 = mp[ip], d1 = mp[ip + 1], d2 = mp[ip + 2], d3 = mp[ip + 3];

        int fz0 = __float_as_int(c0.z), fz1 = __float_as_int(c1.z);
        int fz2 = __float_as_int(c2.z), fz3 = __float_as_int(c3.z);
        int f0 = fz0 & 0x7fffffff, f1 = fz1 & 0x7fffffff;
        int f2 = fz2 & 0x7fffffff, f3 = fz3 & 0x7fffffff;

        // 8 independent exponentials (pipelined MUFU)
        float e00 = EVAL(c0, f0, 0),        e01 = EVAL(c1, f1, 0);
        float e02 = EVAL(c2, f2, 0),        e03 = EVAL(c3, f3, 0);
        float e10 = EVAL(c0, f0, 32 * XPAD), e11 = EVAL(c1, f1, 32 * XPAD);
        float e12 = EVAL(c2, f2, 32 * XPAD), e13 = EVAL(c3, f3, 32 * XPAD);

        // branchless p-chains with SEL resets; q's keep pre-reset values
        float q00 = fmaf(p0, e00, p0);  p0 = (fz0 < 0) ? 1.f : q00;
        float q01 = fmaf(p0, e01, p0);  p0 = (fz1 < 0) ? 1.f : q01;
        float q02 = fmaf(p0, e02, p0);  p0 = (fz2 < 0) ? 1.f : q02;
        float q03 = fmaf(p0, e03, p0);  p0 = (fz3 < 0) ? 1.f : q03;
        float q10 = fmaf(p1, e10, p1);  p1 = (fz0 < 0) ? 1.f : q10;
        float q11 = fmaf(p1, e11, p1);  p1 = (fz1 < 0) ? 1.f : q11;
        float q12 = fmaf(p1, e12, p1);  p1 = (fz2 < 0) ? 1.f : q12;
        float q13 = fmaf(p1, e13, p1);  p1 = (fz3 < 0) ? 1.f : q13;

        // rare path: flush finished clauses (one warp-uniform branch / 4 atoms)
        if ((fz0 | fz1 | fz2 | fz3) < 0) {
            if (fz0 < 0) { y0 = fmaf(c0.w, rcpa(q00), y0);
                           y1 = fmaf(c0.w, rcpa(q10), y1); }
            if (fz1 < 0) { y0 = fmaf(c1.w, rcpa(q01), y0);
                           y1 = fmaf(c1.w, rcpa(q11), y1); }
            if (fz2 < 0) { y0 = fmaf(c2.w, rcpa(q02), y0);
                           y1 = fmaf(c2.w, rcpa(q12), y1); }
            if (fz3 < 0) { y0 = fmaf(c3.w, rcpa(q03), y0);
                           y1 = fmaf(c3.w, rcpa(q13), y1); }
        }
        c0 = d0; c1 = d1; c2 = d2; c3 = d3;
    }
    for (int i = n4; i < n; ++i) {
        float4 m = mp[i];
        int fz = __float_as_int(m.z);
        int f  = fz & 0x7fffffff;
        float e0 = EVAL(m, f, 0), e1 = EVAL(m, f, 32 * XPAD);
        float q0 = fmaf(p0, e0, p0), q1 = fmaf(p1, e1, p1);
        if (fz < 0) {
            y0 = fmaf(m.w, rcpa(q0), y0);
            y1 = fmaf(m.w, rcpa(q1), y1);
            p0 = 1.f; p1 = 1.f;
        } else { p0 = q0; p1 = q1; }
    }
    // chunk is clause-aligned: last atom always flushes.

    atomicAdd(&ys[lane], y0);
    atomicAdd(&ys[lane + 32], y1);
    __syncthreads();
    if (threadIdx.x < ROWS)
        y[rowBase + threadIdx.x] = ys[threadIdx.x];   // sole writer per row
}

extern "C" void kernel_launch(void* const* d_in, const int* in_sizes, int n_in,
                              void* d_out, int out_size) {
    const float* x    = (const float*)d_in[0];
    const float* w    = (const float*)d_in[1];
    const float* eta  = (const float*)d_in[2];
    const float* leaf = (const float*)d_in[3];
    const float* gate = (const float*)d_in[4];
    const int*   fid  = (const int*)d_in[5];
    const int*   csgn = (const int*)d_in[6];
    const int*   cids = (const int*)d_in[7];

    const int n_atoms   = in_sizes[1];
    const int n_clauses = in_sizes[3];
    const int batch     = out_size;
    const int nfeat     = in_sizes[0] / batch;
    const int cpc       = n_clauses / NCHUNKS;

    void* empty_ptr = nullptr;
    cudaGetSymbolAddress(&empty_ptr, g_empty);
    cudaMemsetAsync(empty_ptr, 0, NCHUNKS * sizeof(float));

    cln_setup<<<(n_atoms + 255) / 256, 256>>>(w, eta, leaf, gate, fid, csgn,
                                              cids, n_atoms, n_clauses, cpc);

    size_t smem = (size_t)ROWS * XPAD * sizeof(float);
    cudaFuncSetAttribute(cln_main, cudaFuncAttributeMaxDynamicSharedMemorySize,
                         (int)smem);
    cln_main<<<batch / ROWS, THREADS, smem>>>(x, (float*)d_out, nfeat);
}